// round 3
// baseline (speedup 1.0000x reference)
#include <cuda_runtime.h>

#define NN 50000
#define EE 800000
#define IN1 128
#define HC1 256   // H1 * CC
#define H1 4
#define CC 64
#define NEG 0.2f

// ---------------- scratch (device globals; allocation-free) ----------------
__device__ float g_h1[NN * HC1];     // layer1 features h = x@W1
__device__ float g_agg1[NN * HC1];   // relu(layer1 out) = layer2 input
__device__ float g_h2[NN * CC];      // layer2 features
__device__ float g_as1[NN * H1];
__device__ float g_ad1[NN * H1];
__device__ float g_s1[NN * H1];
__device__ float g_as2[NN];
__device__ float g_ad2[NN];
__device__ float g_s2[NN];
__device__ float g_wex1[EE * H1];
__device__ float g_wex2[EE];
__device__ int   g_deg[NN];
__device__ int   g_off[NN + 1];
__device__ int   g_cur[NN];
__device__ int   g_csr_src[EE];
__device__ int   g_csr_dst[EE];
__device__ int   g_is64;

__device__ __forceinline__ float leaky(float v) {
    return v > 0.f ? v : NEG * v;
}

// edge_index may be int32 (JAX x64 disabled) or int64. Detect at runtime.
__global__ void detect_kernel(const void* __restrict__ ei) {
    const unsigned long long* p = (const unsigned long long*)ei;
    int is64 = 1;
    for (int i = 0; i < 64; i++) {
        if ((p[i] >> 32) != 0ull) { is64 = 0; break; }
    }
    g_is64 = is64;
}

__device__ __forceinline__ int edge_at(const void* __restrict__ ei, int idx) {
    if (g_is64) return (int)((const long long*)ei)[idx];
    return ((const int*)ei)[idx];
}

// ---------------- CSR build ----------------
__global__ void zero_deg_kernel() {
    int i = blockIdx.x * blockDim.x + threadIdx.x;
    if (i < NN) g_deg[i] = 0;
}

__global__ void count_kernel(const void* __restrict__ ei) {
    int e = blockIdx.x * blockDim.x + threadIdx.x;
    if (e < EE) {
        int dst = edge_at(ei, EE + e);
        atomicAdd(&g_deg[dst], 1);
    }
}

// single-block exclusive scan over g_deg -> g_off, g_cur
__global__ void scan_kernel() {
    __shared__ int sh[1024];
    __shared__ int carry;
    int tid = threadIdx.x;
    if (tid == 0) carry = 0;
    __syncthreads();
    for (int base = 0; base < NN; base += 1024) {
        int idx = base + tid;
        int v = (idx < NN) ? g_deg[idx] : 0;
        sh[tid] = v;
        __syncthreads();
        #pragma unroll
        for (int o = 1; o < 1024; o <<= 1) {
            int t = (tid >= o) ? sh[tid - o] : 0;
            __syncthreads();
            sh[tid] += t;
            __syncthreads();
        }
        int inc = sh[tid];
        int exc = inc - v;
        if (idx < NN) {
            int val = carry + exc;
            g_off[idx] = val;
            g_cur[idx] = val;
        }
        __syncthreads();
        if (tid == 1023) carry += sh[1023];
        __syncthreads();
    }
    if (tid == 0) g_off[NN] = carry;
}

__global__ void scatter_kernel(const void* __restrict__ ei) {
    int e = blockIdx.x * blockDim.x + threadIdx.x;
    if (e < EE) {
        int src = edge_at(ei, e);
        int dst = edge_at(ei, EE + e);
        int pos = atomicAdd(&g_cur[dst], 1);
        g_csr_src[pos] = src;
    }
}

__global__ void fill_dst_kernel() {
    int i = blockIdx.x * blockDim.x + threadIdx.x;
    if (i < NN) {
        int b = g_off[i], e = g_off[i + 1];
        for (int k = b; k < e; k++) g_csr_dst[k] = i;
    }
}

// ---------------- GEMM: C[M,Nc] = A[M,K] @ B[K,Nc] ----------------
#define TBM 128
#define TBN 64
#define TBK 16
__device__ __forceinline__ void gemm_body(
    const float* __restrict__ A, const float* __restrict__ B,
    float* __restrict__ C, int M, int K, int Nc)
{
    __shared__ float As[TBK][TBM];
    __shared__ float Bs[TBK][TBN];
    int tid = threadIdx.x;
    int tx = tid & 15;   // N dir (4 cols each)
    int ty = tid >> 4;   // M dir (8 rows each)
    int m0 = blockIdx.x * TBM;
    int n0 = blockIdx.y * TBN;

    int arow = tid >> 1;           // 0..127
    int ac4  = (tid & 1) * 2;      // float4 index: 0 or 2
    int brow = tid >> 4;           // 0..15
    int bc4  = tid & 15;           // 0..15

    float acc[8][4];
    #pragma unroll
    for (int i = 0; i < 8; i++)
        #pragma unroll
        for (int j = 0; j < 4; j++) acc[i][j] = 0.f;

    for (int k0 = 0; k0 < K; k0 += TBK) {
        {
            int gr = m0 + arow;
            float4 v0 = make_float4(0.f, 0.f, 0.f, 0.f);
            float4 v1 = v0;
            if (gr < M) {
                const float4* ap = (const float4*)(A + (size_t)gr * K + k0);
                v0 = ap[ac4];
                v1 = ap[ac4 + 1];
            }
            int kb = ac4 * 4;
            As[kb + 0][arow] = v0.x; As[kb + 1][arow] = v0.y;
            As[kb + 2][arow] = v0.z; As[kb + 3][arow] = v0.w;
            As[kb + 4][arow] = v1.x; As[kb + 5][arow] = v1.y;
            As[kb + 6][arow] = v1.z; As[kb + 7][arow] = v1.w;
        }
        {
            const float4* bp = (const float4*)(B + (size_t)(k0 + brow) * Nc + n0);
            *(float4*)&Bs[brow][bc4 * 4] = bp[bc4];
        }
        __syncthreads();
        #pragma unroll
        for (int kk = 0; kk < TBK; kk++) {
            float a[8], b[4];
            *(float4*)&a[0] = *(const float4*)&As[kk][ty * 8];
            *(float4*)&a[4] = *(const float4*)&As[kk][ty * 8 + 4];
            *(float4*)&b[0] = *(const float4*)&Bs[kk][tx * 4];
            #pragma unroll
            for (int i = 0; i < 8; i++)
                #pragma unroll
                for (int j = 0; j < 4; j++)
                    acc[i][j] += a[i] * b[j];
        }
        __syncthreads();
    }
    #pragma unroll
    for (int i = 0; i < 8; i++) {
        int r = m0 + ty * 8 + i;
        if (r < M) {
            float4 v = make_float4(acc[i][0], acc[i][1], acc[i][2], acc[i][3]);
            *(float4*)(C + (size_t)r * Nc + n0 + tx * 4) = v;
        }
    }
}

__global__ __launch_bounds__(256) void gemm1_kernel(
    const float* __restrict__ A, const float* __restrict__ B) {
    gemm_body(A, B, g_h1, NN, IN1, HC1);
}
__global__ __launch_bounds__(256) void gemm2_kernel(
    const float* __restrict__ B) {
    gemm_body(g_agg1, B, g_h2, NN, HC1, CC);
}

// ---------------- alpha kernels: per (node, head) dot products ----------------
__device__ __forceinline__ void alpha_body(
    const float* __restrict__ h, const float* __restrict__ attsrc,
    const float* __restrict__ attdst,
    float* __restrict__ as_, float* __restrict__ ad_, float* __restrict__ s_,
    int H)
{
    int gt = blockIdx.x * blockDim.x + threadIdx.x;
    int warp = gt >> 5;
    int lane = gt & 31;
    if (warp >= NN * H) return;
    int i = warp / H;
    int hh = warp - i * H;
    const float* row = h + (size_t)(i * H + hh) * 64;
    float v0 = row[lane], v1 = row[lane + 32];
    float a0 = attsrc[hh * 64 + lane], a1 = attsrc[hh * 64 + lane + 32];
    float d0 = attdst[hh * 64 + lane], d1 = attdst[hh * 64 + lane + 32];
    float ds = v0 * a0 + v1 * a1;
    float dd = v0 * d0 + v1 * d1;
    #pragma unroll
    for (int o = 16; o > 0; o >>= 1) {
        ds += __shfl_xor_sync(0xFFFFFFFF, ds, o);
        dd += __shfl_xor_sync(0xFFFFFFFF, dd, o);
    }
    if (lane == 0) {
        as_[i * H + hh] = ds;
        ad_[i * H + hh] = dd;
        // self-loop term seeds the softmax denominator (re-written every call)
        s_[i * H + hh] = expf(leaky(ds + dd));
    }
}

__global__ void alpha1_kernel(const float* __restrict__ attsrc,
                              const float* __restrict__ attdst) {
    alpha_body(g_h1, attsrc, attdst, g_as1, g_ad1, g_s1, H1);
}
__global__ void alpha2_kernel(const float* __restrict__ attsrc,
                              const float* __restrict__ attdst) {
    alpha_body(g_h2, attsrc, attdst, g_as2, g_ad2, g_s2, 1);
}

// ---------------- edge weight kernels ----------------
__global__ void edge_kernel_l1() {
    int e = blockIdx.x * blockDim.x + threadIdx.x;
    if (e >= EE) return;
    int src = g_csr_src[e];
    int dst = g_csr_dst[e];
    float4 a = *(const float4*)(g_as1 + src * 4);
    float4 d = *(const float4*)(g_ad1 + dst * 4);
    float4 w;
    w.x = expf(leaky(a.x + d.x));
    w.y = expf(leaky(a.y + d.y));
    w.z = expf(leaky(a.z + d.z));
    w.w = expf(leaky(a.w + d.w));
    *(float4*)(g_wex1 + (size_t)e * 4) = w;
    atomicAdd(&g_s1[dst * 4 + 0], w.x);
    atomicAdd(&g_s1[dst * 4 + 1], w.y);
    atomicAdd(&g_s1[dst * 4 + 2], w.z);
    atomicAdd(&g_s1[dst * 4 + 3], w.w);
}

__global__ void edge_kernel_l2() {
    int e = blockIdx.x * blockDim.x + threadIdx.x;
    if (e >= EE) return;
    int src = g_csr_src[e];
    int dst = g_csr_dst[e];
    float w = expf(leaky(g_as2[src] + g_ad2[dst]));
    g_wex2[e] = w;
    atomicAdd(&g_s2[dst], w);
}

// ---------------- aggregation: one block per dst node ----------------
__global__ __launch_bounds__(256) void agg1_kernel(const float* __restrict__ bias) {
    int i = blockIdx.x;
    int tid = threadIdx.x;          // 0..255
    int hh = tid >> 6;              // head
    int beg = g_off[i];
    int end = g_off[i + 1];
    float acc = 0.f;
    for (int k = beg; k < end; k++) {
        int src = g_csr_src[k];
        float w = g_wex1[(size_t)k * H1 + hh];
        acc += w * g_h1[(size_t)src * HC1 + tid];
    }
    float es = expf(leaky(g_as1[i * H1 + hh] + g_ad1[i * H1 + hh]));
    acc += es * g_h1[(size_t)i * HC1 + tid];
    float o = acc / (g_s1[i * H1 + hh] + 1e-16f) + bias[tid];
    g_agg1[(size_t)i * HC1 + tid] = fmaxf(o, 0.f);
}

__global__ __launch_bounds__(64) void agg2_kernel(const float* __restrict__ bias,
                                                  float* __restrict__ out) {
    int i = blockIdx.x;
    int tid = threadIdx.x;          // 0..63
    int beg = g_off[i];
    int end = g_off[i + 1];
    float acc = 0.f;
    for (int k = beg; k < end; k++) {
        int src = g_csr_src[k];
        acc += g_wex2[k] * g_h2[(size_t)src * CC + tid];
    }
    float es = expf(leaky(g_as2[i] + g_ad2[i]));
    acc += es * g_h2[(size_t)i * CC + tid];
    out[(size_t)i * CC + tid] = acc / (g_s2[i] + 1e-16f) + bias[tid];
}

// ---------------- launch ----------------
extern "C" void kernel_launch(void* const* d_in, const int* in_sizes, int n_in,
                              void* d_out, int out_size) {
    const float* x     = (const float*)d_in[0];
    const void*  ei    = d_in[1];
    const float* W1    = (const float*)d_in[2];
    const float* asrc1 = (const float*)d_in[3];
    const float* adst1 = (const float*)d_in[4];
    const float* b1    = (const float*)d_in[5];
    const float* W2    = (const float*)d_in[6];
    const float* asrc2 = (const float*)d_in[7];
    const float* adst2 = (const float*)d_in[8];
    const float* b2    = (const float*)d_in[9];
    float* out = (float*)d_out;

    // ---- CSR build (shared by both layers) ----
    detect_kernel<<<1, 1>>>(ei);
    zero_deg_kernel<<<(NN + 255) / 256, 256>>>();
    count_kernel<<<(EE + 255) / 256, 256>>>(ei);
    scan_kernel<<<1, 1024>>>();
    scatter_kernel<<<(EE + 255) / 256, 256>>>(ei);
    fill_dst_kernel<<<(NN + 255) / 256, 256>>>();

    // ---- layer 1 ----
    {
        dim3 g((NN + TBM - 1) / TBM, HC1 / TBN);
        gemm1_kernel<<<g, 256>>>(x, W1);
    }
    alpha1_kernel<<<(NN * H1 * 32 + 255) / 256, 256>>>(asrc1, adst1);
    edge_kernel_l1<<<(EE + 255) / 256, 256>>>();
    agg1_kernel<<<NN, 256>>>(b1);

    // ---- layer 2 ----
    {
        dim3 g((NN + TBM - 1) / TBM, CC / TBN);
        gemm2_kernel<<<g, 256>>>(W2);
    }
    alpha2_kernel<<<(NN * 32 + 255) / 256, 256>>>(asrc2, adst2);
    edge_kernel_l2<<<(EE + 255) / 256, 256>>>();
    agg2_kernel<<<NN, 64>>>(b2, out);
}

// round 4
// speedup vs baseline: 1.0798x; 1.0798x over previous
#include <cuda_runtime.h>

#define NN 50000
#define EE 800000
#define IN1 128
#define HC1 256   // H1 * CC
#define H1 4
#define CC 64
#define NEG 0.2f
#define NB_SCAN 196   // ceil(50000/256)

// ---------------- scratch (device globals; allocation-free) ----------------
__device__ float g_h1[NN * HC1];     // layer1 features h = x@W1
__device__ float g_agg1[NN * HC1];   // relu(layer1 out) = layer2 input
__device__ float g_h2[NN * CC];      // layer2 features
__device__ float g_as1[NN * H1];
__device__ float g_ad1[NN * H1];
__device__ float g_s1[NN * H1];
__device__ float g_as2[NN];
__device__ float g_ad2[NN];
__device__ float g_s2[NN];
__device__ float g_wex1[EE * H1];
__device__ float g_wex2[EE];
__device__ int   g_deg[NN];
__device__ int   g_off[NN + 1];
__device__ int   g_cur[NN];
__device__ int   g_csr_src[EE];
__device__ int   g_csr_dst[EE];
__device__ int   g_part[NB_SCAN];
__device__ int   g_pofs[NB_SCAN];
__device__ int   g_is64;

__device__ __forceinline__ float leaky(float v) {
    return v > 0.f ? v : NEG * v;
}

// edge_index may be int32 (JAX x64 disabled) or int64. Detect at runtime.
__global__ void detect_kernel(const void* __restrict__ ei) {
    const unsigned long long* p = (const unsigned long long*)ei;
    int is64 = 1;
    for (int i = 0; i < 64; i++) {
        if ((p[i] >> 32) != 0ull) { is64 = 0; break; }
    }
    g_is64 = is64;
}

__device__ __forceinline__ int edge_at(const void* __restrict__ ei, int idx) {
    if (g_is64) return (int)((const long long*)ei)[idx];
    return ((const int*)ei)[idx];
}

// ---------------- CSR build ----------------
__global__ void zero_deg_kernel() {
    int i = blockIdx.x * blockDim.x + threadIdx.x;
    if (i < NN) g_deg[i] = 0;
}

__global__ void count_kernel(const void* __restrict__ ei) {
    int e = blockIdx.x * blockDim.x + threadIdx.x;
    if (e < EE) {
        int dst = edge_at(ei, EE + e);
        atomicAdd(&g_deg[dst], 1);
    }
}

// ---- two-level scan: partial sums -> scan partials -> apply ----
__global__ __launch_bounds__(256) void scan_partial_kernel() {
    int b = blockIdx.x;
    int tid = threadIdx.x;
    int idx = b * 256 + tid;
    int v = (idx < NN) ? g_deg[idx] : 0;
    #pragma unroll
    for (int o = 16; o > 0; o >>= 1) v += __shfl_xor_sync(0xFFFFFFFF, v, o);
    __shared__ int wsum[8];
    if ((tid & 31) == 0) wsum[tid >> 5] = v;
    __syncthreads();
    if (tid == 0) {
        int s = 0;
        #pragma unroll
        for (int i = 0; i < 8; i++) s += wsum[i];
        g_part[b] = s;
    }
}

__global__ __launch_bounds__(256) void scan_tops_kernel() {
    int tid = threadIdx.x;
    int v = (tid < NB_SCAN) ? g_part[tid] : 0;
    int lane = tid & 31, w = tid >> 5;
    int x = v;
    #pragma unroll
    for (int o = 1; o < 32; o <<= 1) {
        int t = __shfl_up_sync(0xFFFFFFFF, x, o);
        if (lane >= o) x += t;
    }
    __shared__ int wsum[8];
    if (lane == 31) wsum[w] = x;
    __syncthreads();
    if (tid == 0) {
        int run = 0;
        #pragma unroll
        for (int i = 0; i < 8; i++) { int t = wsum[i]; wsum[i] = run; run += t; }
        g_off[NN] = run;   // total edges (== EE)
    }
    __syncthreads();
    if (tid < NB_SCAN) g_pofs[tid] = x - v + wsum[w];
}

__global__ __launch_bounds__(256) void scan_apply_kernel() {
    int b = blockIdx.x;
    int tid = threadIdx.x;
    int idx = b * 256 + tid;
    int v = (idx < NN) ? g_deg[idx] : 0;
    int lane = tid & 31, w = tid >> 5;
    int x = v;
    #pragma unroll
    for (int o = 1; o < 32; o <<= 1) {
        int t = __shfl_up_sync(0xFFFFFFFF, x, o);
        if (lane >= o) x += t;
    }
    __shared__ int wsum[8];
    if (lane == 31) wsum[w] = x;
    __syncthreads();
    if (tid == 0) {
        int run = 0;
        #pragma unroll
        for (int i = 0; i < 8; i++) { int t = wsum[i]; wsum[i] = run; run += t; }
    }
    __syncthreads();
    if (idx < NN) {
        int exc = x - v + wsum[w] + g_pofs[b];
        g_off[idx] = exc;
        g_cur[idx] = exc;
    }
}

__global__ void scatter_kernel(const void* __restrict__ ei) {
    int e = blockIdx.x * blockDim.x + threadIdx.x;
    if (e < EE) {
        int src = edge_at(ei, e);
        int dst = edge_at(ei, EE + e);
        int pos = atomicAdd(&g_cur[dst], 1);
        g_csr_src[pos] = src;
    }
}

__global__ void fill_dst_kernel() {
    int i = blockIdx.x * blockDim.x + threadIdx.x;
    if (i < NN) {
        int b = g_off[i], e = g_off[i + 1];
        for (int k = b; k < e; k++) g_csr_dst[k] = i;
    }
}

// ---------------- GEMM: C[M,Nc] = A[M,K] @ B[K,Nc] ----------------
#define TBM 128
#define TBN 64
#define TBK 16
__device__ __forceinline__ void gemm_body(
    const float* __restrict__ A, const float* __restrict__ B,
    float* __restrict__ C, int M, int K, int Nc)
{
    __shared__ float As[TBK][TBM];
    __shared__ float Bs[TBK][TBN];
    int tid = threadIdx.x;
    int tx = tid & 15;   // N dir (4 cols each)
    int ty = tid >> 4;   // M dir (8 rows each)
    int m0 = blockIdx.x * TBM;
    int n0 = blockIdx.y * TBN;

    int arow = tid >> 1;           // 0..127
    int ac4  = (tid & 1) * 2;      // float4 index: 0 or 2
    int brow = tid >> 4;           // 0..15
    int bc4  = tid & 15;           // 0..15

    float acc[8][4];
    #pragma unroll
    for (int i = 0; i < 8; i++)
        #pragma unroll
        for (int j = 0; j < 4; j++) acc[i][j] = 0.f;

    for (int k0 = 0; k0 < K; k0 += TBK) {
        {
            int gr = m0 + arow;
            float4 v0 = make_float4(0.f, 0.f, 0.f, 0.f);
            float4 v1 = v0;
            if (gr < M) {
                const float4* ap = (const float4*)(A + (size_t)gr * K + k0);
                v0 = ap[ac4];
                v1 = ap[ac4 + 1];
            }
            int kb = ac4 * 4;
            As[kb + 0][arow] = v0.x; As[kb + 1][arow] = v0.y;
            As[kb + 2][arow] = v0.z; As[kb + 3][arow] = v0.w;
            As[kb + 4][arow] = v1.x; As[kb + 5][arow] = v1.y;
            As[kb + 6][arow] = v1.z; As[kb + 7][arow] = v1.w;
        }
        {
            const float4* bp = (const float4*)(B + (size_t)(k0 + brow) * Nc + n0);
            *(float4*)&Bs[brow][bc4 * 4] = bp[bc4];
        }
        __syncthreads();
        #pragma unroll
        for (int kk = 0; kk < TBK; kk++) {
            float a[8], b[4];
            *(float4*)&a[0] = *(const float4*)&As[kk][ty * 8];
            *(float4*)&a[4] = *(const float4*)&As[kk][ty * 8 + 4];
            *(float4*)&b[0] = *(const float4*)&Bs[kk][tx * 4];
            #pragma unroll
            for (int i = 0; i < 8; i++)
                #pragma unroll
                for (int j = 0; j < 4; j++)
                    acc[i][j] += a[i] * b[j];
        }
        __syncthreads();
    }
    #pragma unroll
    for (int i = 0; i < 8; i++) {
        int r = m0 + ty * 8 + i;
        if (r < M) {
            float4 v = make_float4(acc[i][0], acc[i][1], acc[i][2], acc[i][3]);
            *(float4*)(C + (size_t)r * Nc + n0 + tx * 4) = v;
        }
    }
}

__global__ __launch_bounds__(256) void gemm1_kernel(
    const float* __restrict__ A, const float* __restrict__ B) {
    gemm_body(A, B, g_h1, NN, IN1, HC1);
}
__global__ __launch_bounds__(256) void gemm2_kernel(
    const float* __restrict__ B) {
    gemm_body(g_agg1, B, g_h2, NN, HC1, CC);
}

// ---------------- alpha kernels: per (node, head) dot products ----------------
__device__ __forceinline__ void alpha_body(
    const float* __restrict__ h, const float* __restrict__ attsrc,
    const float* __restrict__ attdst,
    float* __restrict__ as_, float* __restrict__ ad_, float* __restrict__ s_,
    int H)
{
    int gt = blockIdx.x * blockDim.x + threadIdx.x;
    int warp = gt >> 5;
    int lane = gt & 31;
    if (warp >= NN * H) return;
    int i = warp / H;
    int hh = warp - i * H;
    const float* row = h + (size_t)(i * H + hh) * 64;
    float v0 = row[lane], v1 = row[lane + 32];
    float a0 = attsrc[hh * 64 + lane], a1 = attsrc[hh * 64 + lane + 32];
    float d0 = attdst[hh * 64 + lane], d1 = attdst[hh * 64 + lane + 32];
    float ds = v0 * a0 + v1 * a1;
    float dd = v0 * d0 + v1 * d1;
    #pragma unroll
    for (int o = 16; o > 0; o >>= 1) {
        ds += __shfl_xor_sync(0xFFFFFFFF, ds, o);
        dd += __shfl_xor_sync(0xFFFFFFFF, dd, o);
    }
    if (lane == 0) {
        as_[i * H + hh] = ds;
        ad_[i * H + hh] = dd;
        // self-loop term seeds the softmax denominator (re-written every call)
        s_[i * H + hh] = expf(leaky(ds + dd));
    }
}

__global__ void alpha1_kernel(const float* __restrict__ attsrc,
                              const float* __restrict__ attdst) {
    alpha_body(g_h1, attsrc, attdst, g_as1, g_ad1, g_s1, H1);
}
__global__ void alpha2_kernel(const float* __restrict__ attsrc,
                              const float* __restrict__ attdst) {
    alpha_body(g_h2, attsrc, attdst, g_as2, g_ad2, g_s2, 1);
}

// ---------------- edge weight kernels ----------------
__global__ void edge_kernel_l1() {
    int e = blockIdx.x * blockDim.x + threadIdx.x;
    if (e >= EE) return;
    int src = g_csr_src[e];
    int dst = g_csr_dst[e];
    float4 a = *(const float4*)(g_as1 + src * 4);
    float4 d = *(const float4*)(g_ad1 + dst * 4);
    float4 w;
    w.x = expf(leaky(a.x + d.x));
    w.y = expf(leaky(a.y + d.y));
    w.z = expf(leaky(a.z + d.z));
    w.w = expf(leaky(a.w + d.w));
    *(float4*)(g_wex1 + (size_t)e * 4) = w;
    atomicAdd(&g_s1[dst * 4 + 0], w.x);
    atomicAdd(&g_s1[dst * 4 + 1], w.y);
    atomicAdd(&g_s1[dst * 4 + 2], w.z);
    atomicAdd(&g_s1[dst * 4 + 3], w.w);
}

__global__ void edge_kernel_l2() {
    int e = blockIdx.x * blockDim.x + threadIdx.x;
    if (e >= EE) return;
    int src = g_csr_src[e];
    int dst = g_csr_dst[e];
    float w = expf(leaky(g_as2[src] + g_ad2[dst]));
    g_wex2[e] = w;
    atomicAdd(&g_s2[dst], w);
}

// ---------------- aggregation: one block per dst node ----------------
__global__ __launch_bounds__(256) void agg1_kernel(const float* __restrict__ bias) {
    int i = blockIdx.x;
    int tid = threadIdx.x;          // 0..255
    int hh = tid >> 6;              // head
    int beg = g_off[i];
    int end = g_off[i + 1];
    float acc = 0.f;
    if (beg < end) {
        int src = g_csr_src[beg];
        float w = g_wex1[(size_t)beg * H1 + hh];
        for (int k = beg; k + 1 < end; k++) {
            int src2 = g_csr_src[k + 1];                 // prefetch
            float w2 = g_wex1[(size_t)(k + 1) * H1 + hh];
            acc += w * g_h1[(size_t)src * HC1 + tid];
            src = src2; w = w2;
        }
        acc += w * g_h1[(size_t)src * HC1 + tid];
    }
    float es = expf(leaky(g_as1[i * H1 + hh] + g_ad1[i * H1 + hh]));
    acc += es * g_h1[(size_t)i * HC1 + tid];
    float o = acc / (g_s1[i * H1 + hh] + 1e-16f) + bias[tid];
    g_agg1[(size_t)i * HC1 + tid] = fmaxf(o, 0.f);
}

// 4 nodes per 256-thread block
__global__ __launch_bounds__(256) void agg2_kernel(const float* __restrict__ bias,
                                                   float* __restrict__ out) {
    int i = blockIdx.x * 4 + (threadIdx.x >> 6);
    int c = threadIdx.x & 63;
    if (i >= NN) return;
    int beg = g_off[i];
    int end = g_off[i + 1];
    float acc = 0.f;
    if (beg < end) {
        int src = g_csr_src[beg];
        float w = g_wex2[beg];
        for (int k = beg; k + 1 < end; k++) {
            int src2 = g_csr_src[k + 1];
            float w2 = g_wex2[k + 1];
            acc += w * g_h2[(size_t)src * CC + c];
            src = src2; w = w2;
        }
        acc += w * g_h2[(size_t)src * CC + c];
    }
    float es = expf(leaky(g_as2[i] + g_ad2[i]));
    acc += es * g_h2[(size_t)i * CC + c];
    out[(size_t)i * CC + c] = acc / (g_s2[i] + 1e-16f) + bias[c];
}

// ---------------- launch ----------------
extern "C" void kernel_launch(void* const* d_in, const int* in_sizes, int n_in,
                              void* d_out, int out_size) {
    const float* x     = (const float*)d_in[0];
    const void*  ei    = d_in[1];
    const float* W1    = (const float*)d_in[2];
    const float* asrc1 = (const float*)d_in[3];
    const float* adst1 = (const float*)d_in[4];
    const float* b1    = (const float*)d_in[5];
    const float* W2    = (const float*)d_in[6];
    const float* asrc2 = (const float*)d_in[7];
    const float* adst2 = (const float*)d_in[8];
    const float* b2    = (const float*)d_in[9];
    float* out = (float*)d_out;

    // ---- CSR build (shared by both layers) ----
    detect_kernel<<<1, 1>>>(ei);
    zero_deg_kernel<<<(NN + 255) / 256, 256>>>();
    count_kernel<<<(EE + 255) / 256, 256>>>(ei);
    scan_partial_kernel<<<NB_SCAN, 256>>>();
    scan_tops_kernel<<<1, 256>>>();
    scan_apply_kernel<<<NB_SCAN, 256>>>();
    scatter_kernel<<<(EE + 255) / 256, 256>>>(ei);
    fill_dst_kernel<<<(NN + 255) / 256, 256>>>();

    // ---- layer 1 ----
    {
        dim3 g((NN + TBM - 1) / TBM, HC1 / TBN);
        gemm1_kernel<<<g, 256>>>(x, W1);
    }
    alpha1_kernel<<<(NN * H1 * 32 + 255) / 256, 256>>>(asrc1, adst1);
    edge_kernel_l1<<<(EE + 255) / 256, 256>>>();
    agg1_kernel<<<NN, 256>>>(b1);

    // ---- layer 2 ----
    {
        dim3 g((NN + TBM - 1) / TBM, CC / TBN);
        gemm2_kernel<<<g, 256>>>(W2);
    }
    alpha2_kernel<<<(NN * 32 + 255) / 256, 256>>>(asrc2, adst2);
    edge_kernel_l2<<<(EE + 255) / 256, 256>>>();
    agg2_kernel<<<(NN + 3) / 4, 256>>>(b2, out);
}